// round 14
// baseline (speedup 1.0000x reference)
#include <cuda_runtime.h>
#include <cuda_fp16.h>

#define OC_N       32
#define TPO        144              // tables per output channel
#define TPB        72               // tables per thread-half
#define IC_N       16
#define PH         34
#define PW         34
#define CH_STRIDE  (PH*PW)          // 1156
#define TILE_ELEMS (IC_N*CH_STRIDE) // 18496 elements
#define NTHREADS   512
#define ROWOFF     (8*PW*2)         // 544 B: +8 rows (LDS immediate offset)

// Block = (batch, oc), 512 threads = 2 table-halves x 256 position-threads.
// Each thread: 4 positions (x-pair at rows r and r+8 via LDS immediate),
// 72 tables. ONE shared tile (fp16, two parity copies). Partials combined
// via a 4KB smem reduction; th=0 half writes the output.
extern __shared__ float smem[];

__global__ void __launch_bounds__(NTHREADS, 2)
lutconv_fused(const float*  __restrict__ inp,
              const float4* __restrict__ w4,
              const int*    __restrict__ mc,
              const int*    __restrict__ mkh,
              const int*    __restrict__ mkw,
              float*        __restrict__ out) {
    const int b    = blockIdx.x >> 5;
    const int oc   = blockIdx.x & 31;
    const int tid  = threadIdx.x;
    const int th   = tid >> 8;        // table half (0/1)
    const int ttid = tid & 255;       // position thread id

    __half* ht    = (__half*)smem;                      // [2*TILE_ELEMS]
    float4* srec  = (float4*)(smem + TILE_ELEMS);       // [TPO]
    float*  scw   = (float*)(srec + TPO);               // [TPO]
    float*  sA    = scw + TPO;                          // [1] (+pad to 16B)
    float4* sred  = (float4*)(sA + 4);                  // [256] reduction

    // --- Per-table precompute (all 144 tables)
    if (tid < TPO) {
        const int t = oc*TPO + tid;
        const float4 wv = w4[t];
        const float bco = 0.25f * (-wv.x + wv.y - wv.z + wv.w);
        const float cco = 0.25f * (-wv.x - wv.y + wv.z + wv.w);
        const float dco = 0.25f * ( wv.x - wv.y - wv.z + wv.w);
        const float aco = 0.25f * ( wv.x + wv.y + wv.z + wv.w);
        const int m0 = 2*t;
        unsigned o0 = (unsigned)(mc[m0  ]*CH_STRIDE + mkh[m0  ]*PW + mkw[m0  ]);
        unsigned o1 = (unsigned)(mc[m0+1]*CH_STRIDE + mkh[m0+1]*PW + mkw[m0+1]);
        o0 = (o0 & 1u) ? (unsigned)TILE_ELEMS + o0 - 1u : o0;   // odd -> copy B
        o1 = (o1 & 1u) ? (unsigned)TILE_ELEMS + o1 - 1u : o1;
        const __half2 bb = __float2half2_rn(bco);
        const __half2 cc = __float2half2_rn(cco);
        const __half2 dd = __float2half2_rn(dco);
        float4 p;
        p.x = __uint_as_float(o0 | (o1 << 16));
        p.y = *(const float*)&bb;
        p.z = *(const float*)&cc;
        p.w = *(const float*)&dd;
        srec[tid] = p;
        scw[tid]  = aco;
    }

    // --- Zero both fp16 tile copies
    {
        const float4 z4 = make_float4(0.f, 0.f, 0.f, 0.f);
        float4* t4 = (float4*)ht;
        #pragma unroll
        for (int i = tid; i < (2*TILE_ELEMS*2)/16; i += NTHREADS) t4[i] = z4;
    }
    __syncthreads();

    // --- Stage interior: f32 -> f16, copy A at e, copy B at e-1
    {
        const float4* ib4 = (const float4*)(inp + (size_t)b * (IC_N*32*32));
        #pragma unroll
        for (int i = tid; i < 4096; i += NTHREADS) {    // 8 iterations
            const float4 v = ib4[i];
            const int j = i << 2;
            const int c = j >> 10;
            const int y = (j >> 5) & 31;
            const int x = j & 31;
            const int e = c*CH_STRIDE + (y+1)*PW + (x+1);
            const __half h0 = __float2half(v.x);
            const __half h1 = __float2half(v.y);
            const __half h2 = __float2half(v.z);
            const __half h3 = __float2half(v.w);
            ht[e  ] = h0; ht[e+1] = h1; ht[e+2] = h2; ht[e+3] = h3;
            ht[TILE_ELEMS + e-1] = h0; ht[TILE_ELEMS + e  ] = h1;
            ht[TILE_ELEMS + e+1] = h2; ht[TILE_ELEMS + e+2] = h3;
        }
    }
    __syncthreads();

    // --- Per-oc constant term
    if (tid < 32) {
        float s = scw[tid] + scw[tid+32] + scw[tid+64] + scw[tid+96]
                + (tid < (TPO - 128) ? scw[tid+128] : 0.0f);
        #pragma unroll
        for (int d = 16; d; d >>= 1) s += __shfl_xor_sync(0xffffffffu, s, d);
        if (tid == 0) *sA = s;
    }
    __syncthreads();

    // --- Main loop: this half's 72 tables, 4 positions/thread.
    const int l    = ttid & 31;
    const int wrp  = ttid >> 5;                    // 0..7
    const int rowA = wrp + ((l >> 4) << 4);        // wrp or wrp+16
    const int x    = (l & 15) << 1;
    const char* tb = (const char*)ht + (rowA*PW + x)*2;
    const float4* cf = srec + th*TPB;

    float f00 = 0.f, f01 = 0.f, f10 = 0.f, f11 = 0.f;

    #pragma unroll 2
    for (int t = 0; t < TPB; t += 2) {
        const float4 pa = cf[t];
        const float4 pb = cf[t+1];
        const unsigned ua = __float_as_uint(pa.x);
        const unsigned ub = __float_as_uint(pb.x);
        const char* a0 = tb + (ua & 0xffffu)*2u;
        const char* a1 = tb + (ua >> 16)*2u;
        const char* b0 = tb + (ub & 0xffffu)*2u;
        const char* b1 = tb + (ub >> 16)*2u;

        const __half2 xa0 = *(const __half2*)(a0);
        const __half2 xa1 = *(const __half2*)(a1);
        const __half2 ya0 = *(const __half2*)(a0 + ROWOFF);
        const __half2 ya1 = *(const __half2*)(a1 + ROWOFF);
        const __half2 xb0 = *(const __half2*)(b0);
        const __half2 xb1 = *(const __half2*)(b1);
        const __half2 yb0 = *(const __half2*)(b0 + ROWOFF);
        const __half2 yb1 = *(const __half2*)(b1 + ROWOFF);

        const __half2 Ba = *(const __half2*)&pa.y;
        const __half2 Ca = *(const __half2*)&pa.z;
        const __half2 Da = *(const __half2*)&pa.w;
        const __half2 Bb = *(const __half2*)&pb.y;
        const __half2 Cb = *(const __half2*)&pb.z;
        const __half2 Db = *(const __half2*)&pb.w;

        __half2 acc01 = __hmul2(Ca, xa1);
        acc01 = __hfma2(xa0, __hfma2(Da, xa1, Ba), acc01);
        acc01 = __hfma2(Cb, xb1, acc01);
        acc01 = __hfma2(xb0, __hfma2(Db, xb1, Bb), acc01);

        __half2 acc23 = __hmul2(Ca, ya1);
        acc23 = __hfma2(ya0, __hfma2(Da, ya1, Ba), acc23);
        acc23 = __hfma2(Cb, yb1, acc23);
        acc23 = __hfma2(yb0, __hfma2(Db, yb1, Bb), acc23);

        const float2 fa = __half22float2(acc01);
        f00 += fa.x; f01 += fa.y;
        const float2 fb = __half22float2(acc23);
        f10 += fb.x; f11 += fb.y;
    }

    // --- Combine the two table-halves via smem, th=0 writes output
    if (th == 1) sred[ttid] = make_float4(f00, f01, f10, f11);
    __syncthreads();
    if (th == 0) {
        const float4 r = sred[ttid];
        const float A = *sA;
        float* ob = out + ((size_t)(b*OC_N + oc)) * 1024;
        float2 r0; r0.x = f00 + r.x + A; r0.y = f01 + r.y + A;
        float2 r1; r1.x = f10 + r.z + A; r1.y = f11 + r.w + A;
        *(float2*)(ob + rowA*32 + x)     = r0;
        *(float2*)(ob + (rowA+8)*32 + x) = r1;
    }
}

// ---------------------------------------------------------------------------
extern "C" void kernel_launch(void* const* d_in, const int* in_sizes, int n_in,
                              void* d_out, int out_size) {
    const float*  inp = (const float*)d_in[0];
    const float4* w4  = (const float4*)d_in[1];
    const int*    mc  = (const int*)d_in[2];
    const int*    mkh = (const int*)d_in[3];
    const int*    mkw = (const int*)d_in[4];
    float*        out = (float*)d_out;

    const int smem_bytes = 2*TILE_ELEMS*(int)sizeof(__half)  // 73984
                         + TPO*(int)sizeof(float4)           // 2304
                         + TPO*(int)sizeof(float)            // 576
                         + 4*(int)sizeof(float)              // sA + pad
                         + 256*(int)sizeof(float4);          // 4096 -> 80976 B
    cudaFuncSetAttribute(lutconv_fused,
                         cudaFuncAttributeMaxDynamicSharedMemorySize, smem_bytes);
    lutconv_fused<<<8*OC_N, NTHREADS, smem_bytes>>>(inp, w4, mc, mkh, mkw, out);
}

// round 15
// speedup vs baseline: 1.0429x; 1.0429x over previous
#include <cuda_runtime.h>
#include <cuda_fp16.h>

#define OC_N       32
#define TPO        144              // tables per output channel
#define TPB        72               // tables per thread-half
#define IC_N       16
#define PH         34
#define PW         34
#define CH_STRIDE  (PH*PW)          // 1156
#define TILE_ELEMS (IC_N*CH_STRIDE) // 18496 elements
#define NTHREADS   512
#define ROWOFF     (8*PW*2)         // 544 B: +8 rows (LDS immediate offset)

static __device__ __forceinline__ __half2 u2h2(unsigned u) {
    __half2 h; *(unsigned*)&h = u; return h;
}

// Block = (batch, oc), 512 threads = 2 table-halves x 256 position-threads.
// 4 positions/thread (x-pair at rows r, r+8 via LDS immediate). fp16 tile,
// two parity copies. Records: uint4 {o0_bytes, o1_bytes, bb, cc} + half2 dd.
// half2 accumulation windowed over 4 tables, fp32 flush per window.
extern __shared__ float smem[];

__global__ void __launch_bounds__(NTHREADS, 2)
lutconv_fused(const float*  __restrict__ inp,
              const float4* __restrict__ w4,
              const int*    __restrict__ mc,
              const int*    __restrict__ mkh,
              const int*    __restrict__ mkw,
              float*        __restrict__ out) {
    const int b    = blockIdx.x >> 5;
    const int oc   = blockIdx.x & 31;
    const int tid  = threadIdx.x;
    const int th   = tid >> 8;        // table half (0/1)
    const int ttid = tid & 255;       // position thread id

    __half*   ht   = (__half*)smem;                     // [2*TILE_ELEMS]
    uint4*    srec = (uint4*)(smem + TILE_ELEMS);       // [TPO]
    unsigned* sdd  = (unsigned*)(srec + TPO);           // [TPO]
    float*    scw  = (float*)(sdd + TPO);               // [TPO]
    float*    sA   = scw + TPO;                         // [1] (+pad)
    float4*   sred = (float4*)(sA + 4);                 // [256]

    // --- Per-table precompute (all 144 tables)
    if (tid < TPO) {
        const int t = oc*TPO + tid;
        const float4 wv = w4[t];
        const float bco = 0.25f * (-wv.x + wv.y - wv.z + wv.w);
        const float cco = 0.25f * (-wv.x - wv.y + wv.z + wv.w);
        const float dco = 0.25f * ( wv.x - wv.y - wv.z + wv.w);
        const float aco = 0.25f * ( wv.x + wv.y + wv.z + wv.w);
        const int m0 = 2*t;
        unsigned o0 = (unsigned)(mc[m0  ]*CH_STRIDE + mkh[m0  ]*PW + mkw[m0  ]);
        unsigned o1 = (unsigned)(mc[m0+1]*CH_STRIDE + mkh[m0+1]*PW + mkw[m0+1]);
        o0 = (o0 & 1u) ? (unsigned)TILE_ELEMS + o0 - 1u : o0;   // odd -> copy B
        o1 = (o1 & 1u) ? (unsigned)TILE_ELEMS + o1 - 1u : o1;
        const __half2 bb = __float2half2_rn(bco);
        const __half2 cc = __float2half2_rn(cco);
        const __half2 dd = __float2half2_rn(dco);
        srec[tid] = make_uint4(o0*2u, o1*2u,
                               *(const unsigned*)&bb, *(const unsigned*)&cc);
        sdd[tid]  = *(const unsigned*)&dd;
        scw[tid]  = aco;
    }

    // --- Zero both fp16 tile copies
    {
        const float4 z4 = make_float4(0.f, 0.f, 0.f, 0.f);
        float4* t4 = (float4*)ht;
        #pragma unroll
        for (int i = tid; i < (2*TILE_ELEMS*2)/16; i += NTHREADS) t4[i] = z4;
    }
    __syncthreads();

    // --- Stage interior: f32 -> f16, copy A at e, copy B at e-1
    {
        const float4* ib4 = (const float4*)(inp + (size_t)b * (IC_N*32*32));
        #pragma unroll
        for (int i = tid; i < 4096; i += NTHREADS) {    // 8 iterations
            const float4 v = ib4[i];
            const int j = i << 2;
            const int c = j >> 10;
            const int y = (j >> 5) & 31;
            const int x = j & 31;
            const int e = c*CH_STRIDE + (y+1)*PW + (x+1);
            const __half h0 = __float2half(v.x);
            const __half h1 = __float2half(v.y);
            const __half h2 = __float2half(v.z);
            const __half h3 = __float2half(v.w);
            ht[e  ] = h0; ht[e+1] = h1; ht[e+2] = h2; ht[e+3] = h3;
            ht[TILE_ELEMS + e-1] = h0; ht[TILE_ELEMS + e  ] = h1;
            ht[TILE_ELEMS + e+1] = h2; ht[TILE_ELEMS + e+2] = h3;
        }
    }
    __syncthreads();

    // --- Per-oc constant term
    if (tid < 32) {
        float s = scw[tid] + scw[tid+32] + scw[tid+64] + scw[tid+96]
                + (tid < (TPO - 128) ? scw[tid+128] : 0.0f);
        #pragma unroll
        for (int d = 16; d; d >>= 1) s += __shfl_xor_sync(0xffffffffu, s, d);
        if (tid == 0) *sA = s;
    }
    __syncthreads();

    // --- Main loop: this half's 72 tables, 4-table windows.
    const int l    = ttid & 31;
    const int wrp  = ttid >> 5;                    // 0..7
    const int rowA = wrp + ((l >> 4) << 4);        // wrp or wrp+16
    const int x    = (l & 15) << 1;
    const char* tb = (const char*)ht + (rowA*PW + x)*2;
    const uint4*    cf = srec + th*TPB;
    const unsigned* cd = sdd  + th*TPB;

    float f00 = 0.f, f01 = 0.f, f10 = 0.f, f11 = 0.f;

    #pragma unroll 1
    for (int t = 0; t < TPB; t += 4) {
        const uint4 r0 = cf[t+0];
        const uint4 r1 = cf[t+1];
        const uint4 r2 = cf[t+2];
        const uint4 r3 = cf[t+3];
        const __half2 D0 = u2h2(cd[t+0]);
        const __half2 D1 = u2h2(cd[t+1]);
        const __half2 D2 = u2h2(cd[t+2]);
        const __half2 D3 = u2h2(cd[t+3]);

        const char* p00 = tb + r0.x;  const char* p01 = tb + r0.y;
        const char* p10 = tb + r1.x;  const char* p11 = tb + r1.y;
        const char* p20 = tb + r2.x;  const char* p21 = tb + r2.y;
        const char* p30 = tb + r3.x;  const char* p31 = tb + r3.y;

        const __half2 x00 = *(const __half2*)(p00);
        const __half2 x01 = *(const __half2*)(p01);
        const __half2 y00 = *(const __half2*)(p00 + ROWOFF);
        const __half2 y01 = *(const __half2*)(p01 + ROWOFF);
        const __half2 x10 = *(const __half2*)(p10);
        const __half2 x11 = *(const __half2*)(p11);
        const __half2 y10 = *(const __half2*)(p10 + ROWOFF);
        const __half2 y11 = *(const __half2*)(p11 + ROWOFF);
        const __half2 x20 = *(const __half2*)(p20);
        const __half2 x21 = *(const __half2*)(p21);
        const __half2 y20 = *(const __half2*)(p20 + ROWOFF);
        const __half2 y21 = *(const __half2*)(p21 + ROWOFF);
        const __half2 x30 = *(const __half2*)(p30);
        const __half2 x31 = *(const __half2*)(p31);
        const __half2 y30 = *(const __half2*)(p30 + ROWOFF);
        const __half2 y31 = *(const __half2*)(p31 + ROWOFF);

        const __half2 B0 = u2h2(r0.z), C0 = u2h2(r0.w);
        const __half2 B1 = u2h2(r1.z), C1 = u2h2(r1.w);
        const __half2 B2 = u2h2(r2.z), C2 = u2h2(r2.w);
        const __half2 B3 = u2h2(r3.z), C3 = u2h2(r3.w);

        // rows rowA (pair 01): window of 4 tables in half2, then fp32 flush
        __half2 a01 = __hfma2(x00, __hfma2(D0, x01, B0), __hmul2(C0, x01));
        a01 = __hfma2(C1, x11, a01);
        a01 = __hfma2(x10, __hfma2(D1, x11, B1), a01);
        a01 = __hfma2(C2, x21, a01);
        a01 = __hfma2(x20, __hfma2(D2, x21, B2), a01);
        a01 = __hfma2(C3, x31, a01);
        a01 = __hfma2(x30, __hfma2(D3, x31, B3), a01);

        // rows rowA+8 (pair 23)
        __half2 a23 = __hfma2(y00, __hfma2(D0, y01, B0), __hmul2(C0, y01));
        a23 = __hfma2(C1, y11, a23);
        a23 = __hfma2(y10, __hfma2(D1, y11, B1), a23);
        a23 = __hfma2(C2, y21, a23);
        a23 = __hfma2(y20, __hfma2(D2, y21, B2), a23);
        a23 = __hfma2(C3, y31, a23);
        a23 = __hfma2(y30, __hfma2(D3, y31, B3), a23);

        const float2 fa = __half22float2(a01);
        f00 += fa.x; f01 += fa.y;
        const float2 fb = __half22float2(a23);
        f10 += fb.x; f11 += fb.y;
    }

    // --- Combine the two table-halves via smem, th=0 writes output
    if (th == 1) sred[ttid] = make_float4(f00, f01, f10, f11);
    __syncthreads();
    if (th == 0) {
        const float4 r = sred[ttid];
        const float A = *sA;
        float* ob = out + ((size_t)(b*OC_N + oc)) * 1024;
        float2 r0; r0.x = f00 + r.x + A; r0.y = f01 + r.y + A;
        float2 r1; r1.x = f10 + r.z + A; r1.y = f11 + r.w + A;
        *(float2*)(ob + rowA*32 + x)     = r0;
        *(float2*)(ob + (rowA+8)*32 + x) = r1;
    }
}

// ---------------------------------------------------------------------------
extern "C" void kernel_launch(void* const* d_in, const int* in_sizes, int n_in,
                              void* d_out, int out_size) {
    const float*  inp = (const float*)d_in[0];
    const float4* w4  = (const float4*)d_in[1];
    const int*    mc  = (const int*)d_in[2];
    const int*    mkh = (const int*)d_in[3];
    const int*    mkw = (const int*)d_in[4];
    float*        out = (float*)d_out;

    const int smem_bytes = 2*TILE_ELEMS*(int)sizeof(__half)  // 73984
                         + TPO*(int)sizeof(uint4)            // 2304
                         + TPO*(int)sizeof(unsigned)         // 576
                         + TPO*(int)sizeof(float)            // 576
                         + 4*(int)sizeof(float)              // sA + pad
                         + 256*(int)sizeof(float4);          // 4096 -> 81552 B
    cudaFuncSetAttribute(lutconv_fused,
                         cudaFuncAttributeMaxDynamicSharedMemorySize, smem_bytes);
    lutconv_fused<<<8*OC_N, NTHREADS, smem_bytes>>>(inp, w4, mc, mkh, mkw, out);
}